// round 15
// baseline (speedup 1.0000x reference)
#include <cuda_runtime.h>
#include <cuda_fp16.h>
#include <cstdint>

#define NB 8
#define NL 256
#define NF 6272
#define NU 32
#define KSPLIT 28

// Scratch (no cudaMalloc allowed)
__device__ float g_p[NB*NL*NU];                      // projections (atomic-accumulated)
__device__ __half g_af[NB*NL*NL];                    // a (softmax) fp16 [b][q][k]
__device__ __half g_xh[(size_t)NB*NL*NF];            // inputs fp16 [b][k][f] (written by k_proj)

// ---------------------------------------------------------------------------
// helpers
// ---------------------------------------------------------------------------
__device__ __forceinline__ uint32_t s2u(const void* p){
    uint32_t a;
    asm("{ .reg .u64 t; cvta.to.shared.u64 t, %1; cvt.u32.u64 %0, t; }" : "=r"(a) : "l"(p));
    return a;
}
__device__ __forceinline__ float tanh_approx(float x){
    float y; asm("tanh.approx.f32 %0, %1;" : "=f"(y) : "f"(x)); return y;
}
__device__ __forceinline__ void ldsm4(uint32_t r[4], uint32_t a){
    asm volatile("ldmatrix.sync.aligned.m8n8.x4.shared.b16 {%0,%1,%2,%3}, [%4];"
                 : "=r"(r[0]), "=r"(r[1]), "=r"(r[2]), "=r"(r[3]) : "r"(a));
}
__device__ __forceinline__ void ldsm4t(uint32_t r[4], uint32_t a){
    asm volatile("ldmatrix.sync.aligned.m8n8.x4.trans.shared.b16 {%0,%1,%2,%3}, [%4];"
                 : "=r"(r[0]), "=r"(r[1]), "=r"(r[2]), "=r"(r[3]) : "r"(a));
}
__device__ __forceinline__ void mma_f16(float c[4], const uint32_t a[4], uint32_t b0, uint32_t b1){
    asm volatile(
        "mma.sync.aligned.m16n8k16.row.col.f32.f16.f16.f32 "
        "{%0,%1,%2,%3}, {%4,%5,%6,%7}, {%8,%9}, {%0,%1,%2,%3};"
        : "+f"(c[0]), "+f"(c[1]), "+f"(c[2]), "+f"(c[3])
        : "r"(a[0]), "r"(a[1]), "r"(a[2]), "r"(a[3]), "r"(b0), "r"(b1));
}
__device__ __forceinline__ uint2 cvt4h(float4 v){
    __half h[4];
    h[0] = __float2half(v.x); h[1] = __float2half(v.y);
    h[2] = __float2half(v.z); h[3] = __float2half(v.w);
    return *(uint2*)h;
}
__device__ __forceinline__ void cp16(uint32_t dst, const void* src){
    asm volatile("cp.async.cg.shared.global [%0], [%1], 16;" :: "r"(dst), "l"(src));
}
__device__ __forceinline__ void cp_commit(){ asm volatile("cp.async.commit_group;"); }
__device__ __forceinline__ void cp_wait1(){ asm volatile("cp.async.wait_group 1;"); }

// ---------------------------------------------------------------------------
// K_proj: g_p += x[rows, fchunk] @ Wt[fchunk, 32]  (fp16 HMMA, atomic partials)
// cp.async fp32 3-stage ring; each thread converts its own bytes.
// Writes g_xh (inputs fp16) as byproduct. grid (16, 28), 256 thr, 3 CTA/SM.
// IDENTICAL to R14.
// ---------------------------------------------------------------------------
#define P_OFF_WF 49152
#define P_OFF_AH 61440
#define P_OFF_BH 71680
#define P_SMEM   74240

__global__ __launch_bounds__(256) void k_proj(const float* __restrict__ inp,
                                              const float* __restrict__ Wt){
    extern __shared__ char sm[];
    const uint32_t smb = s2u(sm);
    const int t = threadIdx.x, wid = t >> 5, l = t & 31;
    const int lr = l & 15, lc = (l >> 4) << 3;
    const int row0 = blockIdx.x * 128;
    const int fb0  = blockIdx.y * 224;

    const int r0t = t >> 3;
    const int colf = (t & 7)*4;

    float acc[4][4];
    #pragma unroll
    for (int i = 0; i < 4; i++)
        #pragma unroll
        for (int j = 0; j < 4; j++) acc[i][j] = 0.f;

    const uint32_t a_ah = smb + P_OFF_AH, a_bh = smb + P_OFF_BH;

    #pragma unroll
    for (int s = 0; s < 2; s++){
        const int fb = fb0 + s*32;
        const uint32_t xst = smb + s*16384;
        const uint32_t wst = smb + P_OFF_WF + s*4096;
        #pragma unroll
        for (int i = 0; i < 4; i++){
            int r = r0t + 32*i;
            cp16(xst + (uint32_t)r*128 + colf*4, inp + (size_t)(row0 + r)*NF + fb + colf);
        }
        cp16(wst + (uint32_t)r0t*128 + colf*4, Wt + (size_t)(fb + r0t)*NU + colf);
        cp_commit();
    }

    for (int s = 0; s < 7; s++){
        cp_wait1();
        const int fb = fb0 + s*32;
        const uint32_t xst = smb + (s % 3)*16384;

        #pragma unroll
        for (int i = 0; i < 4; i++){
            int r = r0t + 32*i;
            float4 v = *(const float4*)(sm + (xst - smb) + (uint32_t)r*128 + colf*4);
            uint2 h = cvt4h(v);
            *(uint2*)(sm + P_OFF_AH + (uint32_t)r*80 + colf*2) = h;
            *(uint2*)&g_xh[(size_t)(row0 + r)*NF + fb + colf] = h;
        }
        {
            float4 v = *(const float4*)(sm + P_OFF_WF + (s%3)*4096 + (uint32_t)r0t*128 + colf*4);
            *(uint2*)(sm + P_OFF_BH + (uint32_t)r0t*80 + colf*2) = cvt4h(v);
        }

        if (s < 5){
            const int fbn = fb0 + (s+2)*32;
            const uint32_t xs2 = smb + ((s+2) % 3)*16384;
            const uint32_t ws2 = smb + P_OFF_WF + ((s+2) % 3)*4096;
            #pragma unroll
            for (int i = 0; i < 4; i++){
                int r = r0t + 32*i;
                cp16(xs2 + (uint32_t)r*128 + colf*4, inp + (size_t)(row0 + r)*NF + fbn + colf);
            }
            cp16(ws2 + (uint32_t)r0t*128 + colf*4, Wt + (size_t)(fbn + r0t)*NU + colf);
        }
        cp_commit();

        __syncthreads();

        #pragma unroll
        for (int ks = 0; ks < 32; ks += 16){
            uint32_t fa[4];
            ldsm4(fa, a_ah + ((wid*16 + lr)*40 + ks + lc)*2);
            uint32_t fb4[8];
            ldsm4t(fb4 + 0, a_bh + ((ks + lr)*40 + 0  + lc)*2);
            ldsm4t(fb4 + 4, a_bh + ((ks + lr)*40 + 16 + lc)*2);
            #pragma unroll
            for (int ng = 0; ng < 4; ng++)
                mma_f16(acc[ng], fa, fb4[ng*2], fb4[ng*2+1]);
        }
        __syncthreads();
    }

    const int r0 = row0 + wid*16 + (l >> 2);
    const int c0 = (l & 3)*2;
    #pragma unroll
    for (int ng = 0; ng < 4; ng++){
        atomicAdd(&g_p[(size_t)r0*NU + ng*8 + c0],     acc[ng][0]);
        atomicAdd(&g_p[(size_t)r0*NU + ng*8 + c0 + 1], acc[ng][1]);
        atomicAdd(&g_p[(size_t)(r0+8)*NU + ng*8 + c0],     acc[ng][2]);
        atomicAdd(&g_p[(size_t)(r0+8)*NU + ng*8 + c0 + 1], acc[ng][3]);
    }
}

// ---------------------------------------------------------------------------
// K_attn: block handles (b, 16 queries). grid (16, 8). IDENTICAL to R14.
// ---------------------------------------------------------------------------
__global__ __launch_bounds__(256) void k_attn(const float* __restrict__ bh,
                                              const float* __restrict__ Wa,
                                              const float* __restrict__ ba){
    __shared__ float ps[NL][33];
    __shared__ float pqb[16][32];
    __shared__ float was[32];
    __shared__ float red[8][16];
    __shared__ float inv[16];

    const int t = threadIdx.x;
    const int b = blockIdx.y;
    const int q0 = blockIdx.x * 16;
    const float* pb = g_p + b*NL*NU;
    const float ba0 = ba[0];

    #pragma unroll
    for (int i = 0; i < 32; i++){
        int idx = t + i*256;
        ps[idx >> 5][idx & 31] = pb[idx];
    }
    if (t < 32) was[t] = Wa[t];
    #pragma unroll
    for (int i = 0; i < 2; i++){
        int e = t + i*256;
        int j = e >> 5, u = e & 31;
        pqb[j][u] = pb[(q0 + j)*NU + u] + bh[u];
    }
    __syncthreads();

    float e[16];
    #pragma unroll
    for (int j = 0; j < 16; j++){
        float acc = 0.f;
        #pragma unroll
        for (int u = 0; u < 32; u++)
            acc = fmaf(was[u], tanh_approx(pqb[j][u] + ps[t][u]), acc);
        float alpha = acc + ba0;
        float sg = 1.f / (1.f + __expf(-alpha));
        e[j] = __expf(sg);
    }

    #pragma unroll
    for (int j = 0; j < 16; j++){
        float w = e[j];
        #pragma unroll
        for (int o = 16; o > 0; o >>= 1) w += __shfl_xor_sync(0xffffffffu, w, o);
        if ((t & 31) == 0) red[t >> 5][j] = w;
    }
    __syncthreads();
    if (t < 16){
        float tot = 0.f;
        #pragma unroll
        for (int w = 0; w < 8; w++) tot += red[w][t];
        inv[t] = 1.f / tot;
    }
    __syncthreads();

    #pragma unroll
    for (int j = 0; j < 16; j++)
        g_af[(size_t)b*NL*NL + (size_t)(q0 + j)*NL + t] = __float2half(e[j] * inv[j]);
}

// ---------------------------------------------------------------------------
// K_out: out[b,q,f] = sum_k a[b,q,k]*x[b,k,f]   (single fp16 HMMA term)
// NEW: BM=128, BN=64, BK=64; 8 warps 4(M)x2(N), warp tile 32x32;
// 2-stage cp.async.cg ring; 3 CTA/SM (launch_bounds(256,3)).
// grid (98, 2, 8), 256 threads.
// ---------------------------------------------------------------------------
// stage layout (bytes): Af 128*72*2 = 18432 | Bf 64*72*2 = 9216 -> 27648
#define STG    27648
#define OFF_B  18432
#define K3_SMEM (2*STG)

__global__ __launch_bounds__(256, 3) void k_out(float* __restrict__ out){
    extern __shared__ char sm[];
    const uint32_t smb = s2u(sm);
    const int t = threadIdx.x, wid = t >> 5, l = t & 31;
    const int lr = l & 15, lc = (l >> 4) << 3;
    const int b  = blockIdx.z;
    const int q0 = blockIdx.y * 128;
    const int f0 = blockIdx.x * 64;
    const int warp_m = wid >> 1, warp_n = wid & 1;   // 4 x 2

    const __half* gaf = g_af + ((size_t)b*NL + q0)*NL;
    const __half* gx  = g_xh + (size_t)b*NL*NF + f0;

    // A staging: 128 rows x 64 halves = 1024 x 16B -> 4 cp16/thread
    int aR[4];
    #pragma unroll
    for (int i = 0; i < 4; i++) aR[i] = (t + i*256) >> 3;   // 0..127
    const int aC = (t & 7)*8;                               // halves
    // B staging: 64 rows x 64 halves = 512 x 16B -> 2 cp16/thread
    int bR[2];
    #pragma unroll
    for (int i = 0; i < 2; i++) bR[i] = (t + i*256) >> 3;   // 0..63
    const int bC = (t & 7)*8;                               // halves

    float acc[2][4][4];
    #pragma unroll
    for (int mt = 0; mt < 2; mt++)
        #pragma unroll
        for (int ng = 0; ng < 4; ng++)
            #pragma unroll
            for (int k = 0; k < 4; k++) acc[mt][ng][k] = 0.f;

    // prologue: chunks 0,1 -> stages 0,1
    #pragma unroll
    for (int c = 0; c < 2; c++){
        const uint32_t st = smb + c*STG;
        const int k0 = c*64;
        #pragma unroll
        for (int i = 0; i < 4; i++)
            cp16(st + (uint32_t)aR[i]*144 + aC*2, gaf + (size_t)aR[i]*NL + k0 + aC);
        #pragma unroll
        for (int i = 0; i < 2; i++)
            cp16(st + OFF_B + (uint32_t)bR[i]*144 + bC*2, gx + (size_t)(k0 + bR[i])*NF + bC);
        cp_commit();
    }

    for (int c = 0; c < 4; c++){
        cp_wait1();            // in-order retirement: chunk c's group complete
        __syncthreads();       // visible; all warps done reading stage (c)%2 from iter c-2

        const uint32_t base = smb + (c & 1)*STG;
        #pragma unroll
        for (int ks = 0; ks < 64; ks += 16){
            uint32_t fb4[8];
            ldsm4t(fb4 + 0, base + OFF_B + ((ks + lr)*72 + warp_n*32 + 0  + lc)*2);
            ldsm4t(fb4 + 4, base + OFF_B + ((ks + lr)*72 + warp_n*32 + 16 + lc)*2);
            #pragma unroll
            for (int mt = 0; mt < 2; mt++){
                uint32_t fa[4];
                ldsm4(fa, base + ((warp_m*32 + mt*16 + lr)*72 + ks + lc)*2);
                #pragma unroll
                for (int ng = 0; ng < 4; ng++)
                    mma_f16(acc[mt][ng], fa, fb4[ng*2], fb4[ng*2+1]);
            }
        }
        __syncthreads();       // all warps done with stage c%2

        if (c < 2){            // refill stage c%2 with chunk c+2
            const int k0 = (c+2)*64;
            #pragma unroll
            for (int i = 0; i < 4; i++)
                cp16(base + (uint32_t)aR[i]*144 + aC*2, gaf + (size_t)aR[i]*NL + k0 + aC);
            #pragma unroll
            for (int i = 0; i < 2; i++)
                cp16(base + OFF_B + (uint32_t)bR[i]*144 + bC*2, gx + (size_t)(k0 + bR[i])*NF + bC);
        }
        cp_commit();           // in-order retirement keeps wait1 sound
    }

    // epilogue
    const int c0 = (l & 3)*2;
    #pragma unroll
    for (int mt = 0; mt < 2; mt++){
        const int row = q0 + warp_m*32 + mt*16 + (l >> 2);
        #pragma unroll
        for (int ng = 0; ng < 4; ng++){
            const int col = f0 + warp_n*32 + ng*8 + c0;
            *(float2*)&out[((size_t)(b*NL + row))*NF + col] =
                make_float2(acc[mt][ng][0], acc[mt][ng][1]);
            *(float2*)&out[((size_t)(b*NL + row + 8))*NF + col] =
                make_float2(acc[mt][ng][2], acc[mt][ng][3]);
        }
    }
}

// ---------------------------------------------------------------------------
extern "C" void kernel_launch(void* const* d_in, const int* in_sizes, int n_in,
                              void* d_out, int out_size){
    const float* inp = (const float*)d_in[0];
    const float* Wt  = (const float*)d_in[1];
    const float* bh  = (const float*)d_in[2];
    const float* Wa  = (const float*)d_in[3];
    const float* ba  = (const float*)d_in[4];
    float* out = (float*)d_out;

    static bool attr_set = false;
    if (!attr_set){
        cudaFuncSetAttribute(k_out, cudaFuncAttributeMaxDynamicSharedMemorySize, K3_SMEM);
        cudaFuncSetAttribute(k_proj, cudaFuncAttributeMaxDynamicSharedMemorySize, P_SMEM);
        attr_set = true;
    }

    void* gp_addr = nullptr;
    cudaGetSymbolAddress(&gp_addr, g_p);
    cudaMemsetAsync(gp_addr, 0, sizeof(float)*NB*NL*NU);

    k_proj<<<dim3(16, KSPLIT), 256, P_SMEM>>>(inp, Wt);
    k_attn<<<dim3(NL/16, NB), 256>>>(bh, Wa, ba);
    k_out<<<dim3(NF/64, NL/128, NB), 256, K3_SMEM>>>(out);
}

// round 16
// speedup vs baseline: 1.0515x; 1.0515x over previous
#include <cuda_runtime.h>
#include <cuda_fp16.h>
#include <cstdint>

#define NB 8
#define NL 256
#define NF 6272
#define NU 32
#define KSPLIT 28

// Scratch (no cudaMalloc allowed)
__device__ float g_p[NB*NL*NU];                      // projections (atomic-accumulated)
__device__ __half g_af[NB*NL*NL];                    // a (softmax) fp16 [b][q][k]
__device__ __half g_xh[(size_t)NB*NL*NF];            // inputs fp16 [b][k][f] (written by k_proj)

// ---------------------------------------------------------------------------
// helpers
// ---------------------------------------------------------------------------
__device__ __forceinline__ uint32_t s2u(const void* p){
    uint32_t a;
    asm("{ .reg .u64 t; cvta.to.shared.u64 t, %1; cvt.u32.u64 %0, t; }" : "=r"(a) : "l"(p));
    return a;
}
__device__ __forceinline__ float tanh_approx(float x){
    float y; asm("tanh.approx.f32 %0, %1;" : "=f"(y) : "f"(x)); return y;
}
__device__ __forceinline__ void ldsm4(uint32_t r[4], uint32_t a){
    asm volatile("ldmatrix.sync.aligned.m8n8.x4.shared.b16 {%0,%1,%2,%3}, [%4];"
                 : "=r"(r[0]), "=r"(r[1]), "=r"(r[2]), "=r"(r[3]) : "r"(a));
}
__device__ __forceinline__ void ldsm4t(uint32_t r[4], uint32_t a){
    asm volatile("ldmatrix.sync.aligned.m8n8.x4.trans.shared.b16 {%0,%1,%2,%3}, [%4];"
                 : "=r"(r[0]), "=r"(r[1]), "=r"(r[2]), "=r"(r[3]) : "r"(a));
}
__device__ __forceinline__ void mma_f16(float c[4], const uint32_t a[4], uint32_t b0, uint32_t b1){
    asm volatile(
        "mma.sync.aligned.m16n8k16.row.col.f32.f16.f16.f32 "
        "{%0,%1,%2,%3}, {%4,%5,%6,%7}, {%8,%9}, {%0,%1,%2,%3};"
        : "+f"(c[0]), "+f"(c[1]), "+f"(c[2]), "+f"(c[3])
        : "r"(a[0]), "r"(a[1]), "r"(a[2]), "r"(a[3]), "r"(b0), "r"(b1));
}
__device__ __forceinline__ uint2 cvt4h(float4 v){
    __half h[4];
    h[0] = __float2half(v.x); h[1] = __float2half(v.y);
    h[2] = __float2half(v.z); h[3] = __float2half(v.w);
    return *(uint2*)h;
}
__device__ __forceinline__ void cp16(uint32_t dst, const void* src){
    asm volatile("cp.async.cg.shared.global [%0], [%1], 16;" :: "r"(dst), "l"(src));
}
__device__ __forceinline__ void cp_commit(){ asm volatile("cp.async.commit_group;"); }
__device__ __forceinline__ void cp_wait1(){ asm volatile("cp.async.wait_group 1;"); }
__device__ __forceinline__ void stg_cs_f2(float* p, float2 v){
    asm volatile("st.global.cs.v2.f32 [%0], {%1, %2};" :: "l"(p), "f"(v.x), "f"(v.y) : "memory");
}

// ---------------------------------------------------------------------------
// K_proj (R13 variant — best measured 15.9us): fp16 HMMA, atomic partials,
// double-buffered static smem, register prefetch, one barrier/iter.
// Writes g_xh (inputs fp16) as byproduct. grid (16, 28), 256 threads.
// ---------------------------------------------------------------------------
__global__ __launch_bounds__(256) void k_proj(const float* __restrict__ inp,
                                              const float* __restrict__ Wt){
    __shared__ __half Ah[2][128][40];
    __shared__ __half Bh[2][32][40];
    const int t = threadIdx.x, wid = t >> 5, l = t & 31;
    const int lr = l & 15, lc = (l >> 4) << 3;
    const int row0 = blockIdx.x * 128;
    const int fb0  = blockIdx.y * 224;

    const int arR[4] = { (t+0)>>3, (t+256)>>3, (t+512)>>3, (t+768)>>3 };
    const int arC    = (t & 7)*4;
    const int wrR    = t >> 3, wrC = (t & 7)*4;

    float acc[4][4];
    #pragma unroll
    for (int i = 0; i < 4; i++)
        #pragma unroll
        for (int j = 0; j < 4; j++) acc[i][j] = 0.f;

    const uint32_t a_ah = s2u(Ah), a_bh = s2u(Bh);

    float4 xv[4], wv;
    #pragma unroll
    for (int i = 0; i < 4; i++)
        xv[i] = *(const float4*)(inp + (size_t)(row0 + arR[i])*NF + fb0 + arC);
    wv = *(const float4*)(Wt + (size_t)(fb0 + wrR)*NU + wrC);

    for (int s = 0; s < 7; s++){
        const int fb = fb0 + s*32;
        const int cur = s & 1;
        #pragma unroll
        for (int i = 0; i < 4; i++){
            uint2 h = cvt4h(xv[i]);
            *(uint2*)&Ah[cur][arR[i]][arC] = h;
            *(uint2*)&g_xh[(size_t)(row0 + arR[i])*NF + fb + arC] = h;
        }
        *(uint2*)&Bh[cur][wrR][wrC] = cvt4h(wv);

        if (s < 6){
            const int fbn = fb0 + (s+1)*32;
            #pragma unroll
            for (int i = 0; i < 4; i++)
                xv[i] = *(const float4*)(inp + (size_t)(row0 + arR[i])*NF + fbn + arC);
            wv = *(const float4*)(Wt + (size_t)(fbn + wrR)*NU + wrC);
        }
        __syncthreads();

        const uint32_t ab = a_ah + cur*10240;
        const uint32_t bb = a_bh + cur*2560;
        #pragma unroll
        for (int ks = 0; ks < 32; ks += 16){
            uint32_t fa[4];
            ldsm4(fa, ab + ((wid*16 + lr)*40 + ks + lc)*2);
            uint32_t fb4[8];
            ldsm4t(fb4 + 0, bb + ((ks + lr)*40 + 0  + lc)*2);
            ldsm4t(fb4 + 4, bb + ((ks + lr)*40 + 16 + lc)*2);
            #pragma unroll
            for (int ng = 0; ng < 4; ng++)
                mma_f16(acc[ng], fa, fb4[ng*2], fb4[ng*2+1]);
        }
    }
    const int r0 = row0 + wid*16 + (l >> 2);
    const int c0 = (l & 3)*2;
    #pragma unroll
    for (int ng = 0; ng < 4; ng++){
        atomicAdd(&g_p[(size_t)r0*NU + ng*8 + c0],     acc[ng][0]);
        atomicAdd(&g_p[(size_t)r0*NU + ng*8 + c0 + 1], acc[ng][1]);
        atomicAdd(&g_p[(size_t)(r0+8)*NU + ng*8 + c0],     acc[ng][2]);
        atomicAdd(&g_p[(size_t)(r0+8)*NU + ng*8 + c0 + 1], acc[ng][3]);
    }
}

// ---------------------------------------------------------------------------
// K_attn: block handles (b, 16 queries). grid (16, 8). IDENTICAL to R14.
// ---------------------------------------------------------------------------
__global__ __launch_bounds__(256) void k_attn(const float* __restrict__ bh,
                                              const float* __restrict__ Wa,
                                              const float* __restrict__ ba){
    __shared__ float ps[NL][33];
    __shared__ float pqb[16][32];
    __shared__ float was[32];
    __shared__ float red[8][16];
    __shared__ float inv[16];

    const int t = threadIdx.x;
    const int b = blockIdx.y;
    const int q0 = blockIdx.x * 16;
    const float* pb = g_p + b*NL*NU;
    const float ba0 = ba[0];

    #pragma unroll
    for (int i = 0; i < 32; i++){
        int idx = t + i*256;
        ps[idx >> 5][idx & 31] = pb[idx];
    }
    if (t < 32) was[t] = Wa[t];
    #pragma unroll
    for (int i = 0; i < 2; i++){
        int e = t + i*256;
        int j = e >> 5, u = e & 31;
        pqb[j][u] = pb[(q0 + j)*NU + u] + bh[u];
    }
    __syncthreads();

    float e[16];
    #pragma unroll
    for (int j = 0; j < 16; j++){
        float acc = 0.f;
        #pragma unroll
        for (int u = 0; u < 32; u++)
            acc = fmaf(was[u], tanh_approx(pqb[j][u] + ps[t][u]), acc);
        float alpha = acc + ba0;
        float sg = 1.f / (1.f + __expf(-alpha));
        e[j] = __expf(sg);
    }

    #pragma unroll
    for (int j = 0; j < 16; j++){
        float w = e[j];
        #pragma unroll
        for (int o = 16; o > 0; o >>= 1) w += __shfl_xor_sync(0xffffffffu, w, o);
        if ((t & 31) == 0) red[t >> 5][j] = w;
    }
    __syncthreads();
    if (t < 16){
        float tot = 0.f;
        #pragma unroll
        for (int w = 0; w < 8; w++) tot += red[w][t];
        inv[t] = 1.f / tot;
    }
    __syncthreads();

    #pragma unroll
    for (int j = 0; j < 16; j++)
        g_af[(size_t)b*NL*NL + (size_t)(q0 + j)*NL + t] = __float2half(e[j] * inv[j]);
}

// ---------------------------------------------------------------------------
// K_out: IDENTICAL to R14 best (BM=128, BN=128, BK=64; 8 warps 2x4, 64x32;
// 3-stage cp.async.cg ring, one wait_group(1)+barrier/chunk; 2 CTA/SM),
// except epilogue uses st.global.cs (streaming; out never re-read).
// grid (49, 2, 8), 256 threads.
// ---------------------------------------------------------------------------
#define STG    35840
#define OFF_B  18432
#define K3_SMEM (3*STG)

__global__ __launch_bounds__(256, 2) void k_out(float* __restrict__ out){
    extern __shared__ char sm[];
    const uint32_t smb = s2u(sm);
    const int t = threadIdx.x, wid = t >> 5, l = t & 31;
    const int lr = l & 15, lc = (l >> 4) << 3;
    const int b  = blockIdx.z;
    const int q0 = blockIdx.y * 128;
    const int f0 = blockIdx.x * 128;
    const int warp_m = wid >> 2, warp_n = wid & 3;

    const __half* gaf = g_af + ((size_t)b*NL + q0)*NL;
    const __half* gx  = g_xh + (size_t)b*NL*NF + f0;

    int aR[4];
    #pragma unroll
    for (int i = 0; i < 4; i++) aR[i] = (t + i*256) >> 3;
    const int aC = (t & 7)*8;
    int bR[4];
    #pragma unroll
    for (int i = 0; i < 4; i++) bR[i] = (t + i*256) >> 4;
    const int bC = (t & 15)*8;

    float acc[4][4][4];
    #pragma unroll
    for (int mt = 0; mt < 4; mt++)
        #pragma unroll
        for (int ng = 0; ng < 4; ng++)
            #pragma unroll
            for (int k = 0; k < 4; k++) acc[mt][ng][k] = 0.f;

    #pragma unroll
    for (int c = 0; c < 2; c++){
        const uint32_t st = smb + c*STG;
        const int k0 = c*64;
        #pragma unroll
        for (int i = 0; i < 4; i++){
            cp16(st + (uint32_t)aR[i]*144 + aC*2,          gaf + (size_t)aR[i]*NL + k0 + aC);
            cp16(st + OFF_B + (uint32_t)bR[i]*272 + bC*2,  gx + (size_t)(k0 + bR[i])*NF + bC);
        }
        cp_commit();
    }

    for (int c = 0; c < 4; c++){
        cp_wait1();
        __syncthreads();

        if (c < 2){
            const uint32_t st = smb + ((c+2)%3)*STG;
            const int k0 = (c+2)*64;
            #pragma unroll
            for (int i = 0; i < 4; i++){
                cp16(st + (uint32_t)aR[i]*144 + aC*2,         gaf + (size_t)aR[i]*NL + k0 + aC);
                cp16(st + OFF_B + (uint32_t)bR[i]*272 + bC*2, gx + (size_t)(k0 + bR[i])*NF + bC);
            }
        }
        cp_commit();

        const uint32_t base = smb + (c % 3)*STG;
        #pragma unroll
        for (int ks = 0; ks < 64; ks += 16){
            uint32_t fb4[8];
            ldsm4t(fb4 + 0, base + OFF_B + ((ks + lr)*136 + warp_n*32 + 0  + lc)*2);
            ldsm4t(fb4 + 4, base + OFF_B + ((ks + lr)*136 + warp_n*32 + 16 + lc)*2);
            #pragma unroll
            for (int mt = 0; mt < 4; mt++){
                uint32_t fa[4];
                ldsm4(fa, base + ((warp_m*64 + mt*16 + lr)*72 + ks + lc)*2);
                #pragma unroll
                for (int ng = 0; ng < 4; ng++)
                    mma_f16(acc[mt][ng], fa, fb4[ng*2], fb4[ng*2+1]);
            }
        }
    }

    const int c0 = (l & 3)*2;
    #pragma unroll
    for (int mt = 0; mt < 4; mt++){
        const int row = q0 + warp_m*64 + mt*16 + (l >> 2);
        #pragma unroll
        for (int ng = 0; ng < 4; ng++){
            const int col = f0 + warp_n*32 + ng*8 + c0;
            stg_cs_f2(&out[((size_t)(b*NL + row))*NF + col],
                      make_float2(acc[mt][ng][0], acc[mt][ng][1]));
            stg_cs_f2(&out[((size_t)(b*NL + row + 8))*NF + col],
                      make_float2(acc[mt][ng][2], acc[mt][ng][3]));
        }
    }
}

// ---------------------------------------------------------------------------
extern "C" void kernel_launch(void* const* d_in, const int* in_sizes, int n_in,
                              void* d_out, int out_size){
    const float* inp = (const float*)d_in[0];
    const float* Wt  = (const float*)d_in[1];
    const float* bh  = (const float*)d_in[2];
    const float* Wa  = (const float*)d_in[3];
    const float* ba  = (const float*)d_in[4];
    float* out = (float*)d_out;

    static bool attr_set = false;
    if (!attr_set){
        cudaFuncSetAttribute(k_out, cudaFuncAttributeMaxDynamicSharedMemorySize, K3_SMEM);
        attr_set = true;
    }

    void* gp_addr = nullptr;
    cudaGetSymbolAddress(&gp_addr, g_p);
    cudaMemsetAsync(gp_addr, 0, sizeof(float)*NB*NL*NU);

    k_proj<<<dim3(16, KSPLIT), 256>>>(inp, Wt);
    k_attn<<<dim3(NL/16, NB), 256>>>(bh, Wa, ba);
    k_out<<<dim3(NF/128, NL/128, NB), 256, K3_SMEM>>>(out);
}